// round 3
// baseline (speedup 1.0000x reference)
#include <cuda_runtime.h>
#include <cuda_bf16.h>
#include <math.h>

// Problem constants
#define BB   64     // batch
#define TT   512    // time
#define EE   256    // embedding
#define HH   256    // hidden
#define G4   1024   // 4*H
#define KK   10     // tags

// -------- device scratch (allocation-free rule: static device globals) -----
__device__ float g_pre[2u * 32768u * 1024u];          // [dir][m=t*64+b][4H]  268MB
__device__ float g_h[2u * 512u * 256u * 64u];         // [dir][t][h][b]       67MB
__device__ float g_logits[512u * 64u * 10u];          // [t][b][k]
__device__ unsigned g_bar;

__global__ void init_kernel() { g_bar = 0u; }

// ---------------------------------------------------------------------------
// Kernel A: fused embedding-gather + GEMM:  g_pre = emb[sent] @ Wih^T + bias
// grid (16, 512, 2): x = n-tile(64), y = t (m-tile is one timestep = 64 batches), z = dir
// ---------------------------------------------------------------------------
__global__ void pregemm_kernel(const int* __restrict__ sent,
                               const float* __restrict__ emb,
                               const float* __restrict__ Wih_f,
                               const float* __restrict__ b_f,
                               const float* __restrict__ Wih_b,
                               const float* __restrict__ b_b) {
    const int dir = blockIdx.z;
    const int t   = blockIdx.y;
    const int n0  = blockIdx.x * 64;
    const float* Wih  = dir ? Wih_b : Wih_f;
    const float* bias = dir ? b_b  : b_f;

    __shared__ float As[16][68];
    __shared__ float Bs[16][68];
    __shared__ int   toks[64];

    const int tid = threadIdx.x;          // 256 threads
    if (tid < 64) toks[tid] = sent[tid * TT + t];   // sent[b][t]
    __syncthreads();

    const int mL = tid >> 2;              // 0..63 (row for A load / B load)
    const int kq = tid & 3;               // 0..3  (float4 within 16-wide k tile)
    const int ty = tid >> 4;              // 0..15
    const int tx = tid & 15;              // 0..15

    float acc[4][4];
#pragma unroll
    for (int i = 0; i < 4; ++i)
#pragma unroll
        for (int j = 0; j < 4; ++j) acc[i][j] = 0.f;

    const float4* emb4 = (const float4*)emb;
    const float4* w4   = (const float4*)Wih;

    for (int k0 = 0; k0 < 256; k0 += 16) {
        float4 av = emb4[(size_t)toks[mL] * 64 + (k0 >> 2) + kq];
        float4 bv = w4[(size_t)(n0 + mL) * 64 + (k0 >> 2) + kq];
        __syncthreads();
        As[kq * 4 + 0][mL] = av.x;  As[kq * 4 + 1][mL] = av.y;
        As[kq * 4 + 2][mL] = av.z;  As[kq * 4 + 3][mL] = av.w;
        Bs[kq * 4 + 0][mL] = bv.x;  Bs[kq * 4 + 1][mL] = bv.y;
        Bs[kq * 4 + 2][mL] = bv.z;  Bs[kq * 4 + 3][mL] = bv.w;
        __syncthreads();
#pragma unroll
        for (int kk = 0; kk < 16; ++kk) {
            float4 a = *(const float4*)&As[kk][ty * 4];
            float4 b = *(const float4*)&Bs[kk][tx * 4];
            acc[0][0] += a.x * b.x; acc[0][1] += a.x * b.y; acc[0][2] += a.x * b.z; acc[0][3] += a.x * b.w;
            acc[1][0] += a.y * b.x; acc[1][1] += a.y * b.y; acc[1][2] += a.y * b.z; acc[1][3] += a.y * b.w;
            acc[2][0] += a.z * b.x; acc[2][1] += a.z * b.y; acc[2][2] += a.z * b.z; acc[2][3] += a.z * b.w;
            acc[3][0] += a.w * b.x; acc[3][1] += a.w * b.y; acc[3][2] += a.w * b.z; acc[3][3] += a.w * b.w;
        }
    }

    float4 bvv = ((const float4*)bias)[(n0 >> 2) + tx];
    float4* out4 = (float4*)g_pre;
#pragma unroll
    for (int i = 0; i < 4; ++i) {
        int b = ty * 4 + i;                 // batch index
        float4 o;
        o.x = acc[i][0] + bvv.x; o.y = acc[i][1] + bvv.y;
        o.z = acc[i][2] + bvv.z; o.w = acc[i][3] + bvv.w;
        out4[((size_t)dir * 32768 + (size_t)t * 64 + b) * 256 + (n0 >> 2) + tx] = o;
    }
}

// ---------------------------------------------------------------------------
// Kernel B: persistent recurrence. 128 blocks = 2 dirs x 64 slices.
// Block owns 4 hidden units (16 Whh rows in smem), all 64 batches.
// h exchanged via g_h[dir][t][h][b] + monotonic grid barrier each step.
// NOTE: bias is already folded into g_pre by pregemm_kernel — do NOT add again.
// dyn smem: sW4 (16KB) | sHT 256x64 (64KB) | sGP 64x16 (4KB)  = 84KB
// ---------------------------------------------------------------------------
__device__ __forceinline__ float sigm(float x) { return 1.f / (1.f + expf(-x)); }

__global__ void lstm_rec_kernel(const float* __restrict__ Whh_f,
                                const float* __restrict__ Whh_b) {
    const int bid   = blockIdx.x;
    const int dir   = bid >> 6;
    const int slice = bid & 63;
    const int hu0   = slice * 4;
    const int tid   = threadIdx.x;        // 256
    const int u     = tid >> 6;           // 0..3 local hidden unit
    const int b     = tid & 63;           // batch

    const float* Whh = dir ? Whh_b : Whh_f;

    extern __shared__ float sm[];
    float4* sW4 = (float4*)sm;            // 16 rows x 64 float4
    float*  sHT = sm + 4096;              // [256][64]
    float*  sGP = sm + 4096 + 16384;      // [64][16]

    // load the 16 Whh rows (gate-major: lr = g*4 + uu)
    const float4* whh4 = (const float4*)Whh;
    for (int idx = tid; idx < 1024; idx += 256) {
        int lr = idx >> 6, kq = idx & 63;
        int g = lr >> 2, uu = lr & 3;
        sW4[idx] = whh4[(size_t)(g * 256 + hu0 + uu) * 64 + kq];
    }

    float c = 0.f;
    const float4* gp4 = (const float4*)g_pre;
    const float4* gh4 = (const float4*)g_h;

    const float4* w0 = sW4 + (0 * 4 + u) * 64;
    const float4* w1 = sW4 + (1 * 4 + u) * 64;
    const float4* w2 = sW4 + (2 * 4 + u) * 64;
    const float4* w3 = sW4 + (3 * 4 + u) * 64;

    for (int it = 0; it < 512; ++it) {
        const int t = dir ? (511 - it) : it;

        // stage previous h (transposed layout [h][b]) into smem
        if (it == 0) {
            float4 z = make_float4(0.f, 0.f, 0.f, 0.f);
            for (int idx = tid; idx < 4096; idx += 256) ((float4*)sHT)[idx] = z;
        } else {
            const int tp = dir ? (t + 1) : (t - 1);
            size_t base = ((size_t)(dir * 512 + tp)) * 4096;  // 256*64/4 float4
            for (int idx = tid; idx < 4096; idx += 256)
                ((float4*)sHT)[idx] = __ldcg(&gh4[base + idx]);
        }
        // stage g_pre slice: sGP[b][g*4 + uu]
        {
            int bb_ = tid >> 2, g = tid & 3;
            float4 v = __ldcg(&gp4[((size_t)dir * 32768 + (size_t)t * 64 + bb_) * 256 + g * 64 + slice]);
            ((float4*)sGP)[bb_ * 4 + g] = v;
        }
        __syncthreads();

        float a0 = sGP[b * 16 + 0 + u];
        float a1 = sGP[b * 16 + 4 + u];
        float a2 = sGP[b * 16 + 8 + u];
        float a3 = sGP[b * 16 + 12 + u];

#pragma unroll 8
        for (int k4 = 0; k4 < 64; ++k4) {
            float h0 = sHT[(k4 * 4 + 0) * 64 + b];
            float h1 = sHT[(k4 * 4 + 1) * 64 + b];
            float h2 = sHT[(k4 * 4 + 2) * 64 + b];
            float h3 = sHT[(k4 * 4 + 3) * 64 + b];
            float4 w;
            w = w0[k4]; a0 += w.x * h0 + w.y * h1 + w.z * h2 + w.w * h3;
            w = w1[k4]; a1 += w.x * h0 + w.y * h1 + w.z * h2 + w.w * h3;
            w = w2[k4]; a2 += w.x * h0 + w.y * h1 + w.z * h2 + w.w * h3;
            w = w3[k4]; a3 += w.x * h0 + w.y * h1 + w.z * h2 + w.w * h3;
        }

        float iv = sigm(a0), fv = sigm(a1), gv = tanhf(a2), ov = sigm(a3);
        c = fv * c + iv * gv;
        float hval = ov * tanhf(c);
        g_h[((size_t)(dir * 512 + t) * 256 + hu0 + u) * 64 + b] = hval;

        __syncthreads();
        if (it < 511) {
            if (tid == 0) {
                __threadfence();
                atomicAdd(&g_bar, 1u);
                unsigned target = 128u * (unsigned)(it + 1);
                volatile unsigned* vb = &g_bar;
                while (*vb < target) { __nanosleep(64); }
            }
            __syncthreads();
            __threadfence();
        }
    }
}

// ---------------------------------------------------------------------------
// Kernel C: logits = concat(h_f, h_b) @ W_out^T + b_out.  grid 512(t), 640 thr
// ---------------------------------------------------------------------------
__global__ void logits_kernel(const float* __restrict__ Wout,
                              const float* __restrict__ bout) {
    const int t = blockIdx.x;
    __shared__ float sWo[10 * 512];   // 20KB
    __shared__ float sCH[64 * 64];    // 16KB
    __shared__ float sBo[10];

    const int tid = threadIdx.x;      // 640
    for (int idx = tid; idx < 5120; idx += 640) sWo[idx] = Wout[idx];
    if (tid < 10) sBo[tid] = bout[tid];

    const int n = tid / 64, b = tid & 63;
    float acc = 0.f;
    const float4* gh4 = (const float4*)g_h;

    for (int ch = 0; ch < 8; ++ch) {
        __syncthreads();
        for (int idx = tid; idx < 1024; idx += 640) {
            int r = idx >> 4, c4 = idx & 15;
            int hidx = ch * 64 + r;          // 0..511 over concat(hf,hb)
            int d = hidx >> 8, hid = hidx & 255;
            ((float4*)sCH)[idx] = gh4[((size_t)(d * 512 + t) * 256 + hid) * 16 + c4];
        }
        __syncthreads();
#pragma unroll 8
        for (int r = 0; r < 64; ++r)
            acc += sWo[n * 512 + ch * 64 + r] * sCH[r * 64 + b];
    }
    g_logits[((size_t)t * 64 + b) * 10 + n] = acc + sBo[n];
}

// ---------------------------------------------------------------------------
// Kernel D: Viterbi forward + backtrack. grid 64 (batch), 32 threads.
// ---------------------------------------------------------------------------
__global__ void viterbi_kernel(const float* __restrict__ trans,
                               float* __restrict__ out) {
    const int b = blockIdx.x, tid = threadIdx.x;
    __shared__ float tr[100];
    __shared__ float tA[10], tB[10];
    __shared__ unsigned char bp[512][10];

    for (int i = tid; i < 100; i += 32) tr[i] = trans[i];
    if (tid < 10) tA[tid] = g_logits[(size_t)(0 * 64 + b) * 10 + tid];
    __syncwarp();

    float* cur = tA;
    float* nxt = tB;
    float lt_next = (tid < 10) ? g_logits[(size_t)(1 * 64 + b) * 10 + tid] : 0.f;

    for (int t = 1; t < 512; ++t) {
        float lt = lt_next;
        if (t + 1 < 512 && tid < 10)
            lt_next = g_logits[(size_t)((t + 1) * 64 + b) * 10 + tid];
        if (tid < 10) {
            float best = cur[0] + tr[0 * 10 + tid];
            int bi = 0;
#pragma unroll
            for (int i = 1; i < 10; ++i) {
                float v = cur[i] + tr[i * 10 + tid];
                if (v > best) { best = v; bi = i; }
            }
            nxt[tid] = lt + best;
            bp[t][tid] = (unsigned char)bi;
        }
        __syncwarp();
        float* tmp = cur; cur = nxt; nxt = tmp;
    }

    if (tid == 0) {
        float best = cur[0]; int last = 0;
#pragma unroll
        for (int i = 1; i < 10; ++i) if (cur[i] > best) { best = cur[i]; last = i; }
        out[b] = best;                               // scores
        float* po = out + 64 + (size_t)b * 512;      // path (as float)
        int tag = last;
        po[511] = (float)tag;
        for (int t = 511; t >= 1; --t) {
            tag = bp[t][tag];
            po[t - 1] = (float)tag;
        }
    }
}

// ---------------------------------------------------------------------------
extern "C" void kernel_launch(void* const* d_in, const int* in_sizes, int n_in,
                              void* d_out, int out_size) {
    const int*   sent  = (const int*)  d_in[0];
    // d_in[1] = lengths (all == T, unused)
    const float* emb   = (const float*)d_in[2];
    const float* Wih_f = (const float*)d_in[3];
    const float* Whh_f = (const float*)d_in[4];
    const float* b_f   = (const float*)d_in[5];
    const float* Wih_b = (const float*)d_in[6];
    const float* Whh_b = (const float*)d_in[7];
    const float* b_b   = (const float*)d_in[8];
    const float* W_out = (const float*)d_in[9];
    const float* b_out = (const float*)d_in[10];
    const float* trans = (const float*)d_in[11];
    float* out = (float*)d_out;

    const size_t rec_smem = (4096 + 16384 + 1024) * sizeof(float);  // 86016
    cudaFuncSetAttribute(lstm_rec_kernel,
                         cudaFuncAttributeMaxDynamicSharedMemorySize,
                         (int)rec_smem);

    init_kernel<<<1, 1>>>();
    pregemm_kernel<<<dim3(16, 512, 2), 256>>>(sent, emb, Wih_f, b_f, Wih_b, b_b);
    lstm_rec_kernel<<<128, 256, rec_smem>>>(Whh_f, Whh_b);
    logits_kernel<<<512, 640>>>(W_out, b_out);
    viterbi_kernel<<<64, 32>>>(trans, out);
}